// round 8
// baseline (speedup 1.0000x reference)
#include <cuda_runtime.h>
#include <cstdint>
#include <cstddef>

// Problem constants: B=64, S=128, D_MODEL=1024, D_INNER=1024
#define M_TOT 8192
#define KDIM  1024
#define NDIM  1024

// Scratch (allowed: __device__ globals, no allocation in kernel_launch)
__device__ __align__(16) float g_emb_r[(size_t)M_TOT * KDIM]; // rna-rounded embeddings
__device__ __align__(16) float g_wq_t[(size_t)KDIM * NDIM];   // Wq^T, rounded  [N][K]
__device__ __align__(16) float g_wv_t[(size_t)KDIM * NDIM];   // Wv^T, rounded
__device__ __align__(16) float g_wo_t[(size_t)KDIM * NDIM];   // Wo^T, rounded
__device__ __align__(16) float g_mid[(size_t)M_TOT * NDIM];   // g = sigmoid(q)*v, rounded

// ---------------------------------------------------------------------------
// helpers
// ---------------------------------------------------------------------------
__device__ __forceinline__ float rna_tf32(float x) {
    uint32_t y;
    asm("cvt.rna.tf32.f32 %0, %1;" : "=r"(y) : "f"(x));
    return __uint_as_float(y);
}

__device__ __forceinline__ void cp16(uint32_t saddr, const void* gptr) {
    asm volatile("cp.async.cg.shared.global [%0], [%1], 16;" :: "r"(saddr), "l"(gptr));
}

__device__ __forceinline__ void ldsm4(uint32_t r[4], uint32_t saddr) {
    asm volatile("ldmatrix.sync.aligned.m8n8.x4.shared.b16 {%0,%1,%2,%3}, [%4];"
                 : "=r"(r[0]), "=r"(r[1]), "=r"(r[2]), "=r"(r[3]) : "r"(saddr));
}

__device__ __forceinline__ void mma_tf32(float c[4], const uint32_t a[4],
                                         uint32_t b0, uint32_t b1) {
    asm volatile(
        "mma.sync.aligned.m16n8k8.row.col.f32.tf32.tf32.f32 "
        "{%0,%1,%2,%3},{%4,%5,%6,%7},{%8,%9},{%0,%1,%2,%3};"
        : "+f"(c[0]), "+f"(c[1]), "+f"(c[2]), "+f"(c[3])
        : "r"(a[0]), "r"(a[1]), "r"(a[2]), "r"(a[3]), "r"(b0), "r"(b1));
}

__device__ __forceinline__ float sigmf(float x) {
    return 1.0f / (1.0f + __expf(-x));
}

// ---------------------------------------------------------------------------
// Prepass kernels
// ---------------------------------------------------------------------------
__global__ void round4_kernel(const float4* __restrict__ in, float4* __restrict__ out, int n) {
    int i = blockIdx.x * blockDim.x + threadIdx.x;
    if (i < n) {
        float4 t = in[i];
        t.x = rna_tf32(t.x); t.y = rna_tf32(t.y);
        t.z = rna_tf32(t.z); t.w = rna_tf32(t.w);
        out[i] = t;
    }
}

// out[n][k] = rna(in[k][n]) for a 1024x1024 matrix
__global__ void transpose_round_kernel(const float* __restrict__ in, float* __restrict__ out) {
    __shared__ float tile[32][33];
    const int bx = blockIdx.x * 32;  // n-block
    const int by = blockIdx.y * 32;  // k-block
    const int tx = threadIdx.x, ty = threadIdx.y;
#pragma unroll
    for (int j = 0; j < 4; j++)
        tile[ty + j * 8][tx] = in[(size_t)(by + ty + j * 8) * NDIM + bx + tx];
    __syncthreads();
#pragma unroll
    for (int j = 0; j < 4; j++)
        out[(size_t)(bx + ty + j * 8) * KDIM + by + tx] = rna_tf32(tile[tx][ty + j * 8]);
}

// ---------------------------------------------------------------------------
// TF32 tensor-core GEMM.
//   DUAL=true : C = rna( sigmoid(A@B0^T + bias0) * (A@B1^T + bias1) )   (g production)
//   DUAL=false: C = A@B0^T + bias0                                       (final output)
// A: [M][K] row-major (pre-rounded).  Bt: [N][K] row-major (transposed, pre-rounded).
// BM=128, BK=32, 256 threads, warp grid 4(m) x 2(n), warp tile 32 x (BN/2).
// ---------------------------------------------------------------------------
template <bool DUAL, int BN>
__global__ __launch_bounds__(256, 1)
void gemm_tf32(const float* __restrict__ A, const float* __restrict__ Bt0,
               const float* __restrict__ Bt1, const float* __restrict__ bias0,
               const float* __restrict__ bias1, float* __restrict__ C) {
    constexpr int BM = 128, BK = 32, THREADS = 256, NSTAGE = 3;
    constexpr int WN = BN / 2;
    constexpr int NT = WN / 8;                 // n8-tiles per warp (4 or 8)
    constexpr int PITCH = 144;                 // bytes per smem row (36 floats: BK + 4 pad)
    constexpr int A_BYTES = BM * PITCH;        // 18432
    constexpr int B_BYTES = BN * PITCH;
    constexpr int NB = DUAL ? 2 : 1;
    constexpr int STAGE = A_BYTES + B_BYTES * NB;
    constexpr int KT = KDIM / BK;              // 32
    constexpr int ALD = BM * 8 / THREADS;      // 4
    constexpr int BLD = BN * 8 / THREADS;      // 2 (BN=64) or 4 (BN=128)

    extern __shared__ char smem[];
    const int tid  = threadIdx.x;
    const int lane = tid & 31, warp = tid >> 5;
    const int wm = warp >> 1, wn = warp & 1;
    const int mBase = blockIdx.y * BM, nBase = blockIdx.x * BN;

    const uint32_t sBase = (uint32_t)__cvta_generic_to_shared(smem);

    // lane-dependent ldmatrix source offsets (bytes within a stage)
    const int lt = lane >> 3, lr = lane & 7;
    const uint32_t aOff = (uint32_t)((wm * 32 + (lt & 1) * 8 + lr) * PITCH + (lt >> 1) * 16);
    const uint32_t bOff = (uint32_t)(A_BYTES + (wn * WN + (lt >> 1) * 8 + lr) * PITCH + (lt & 1) * 16);

    auto load_stage = [&](int st, int k0) {
        const uint32_t sb = sBase + st * STAGE;
#pragma unroll
        for (int i = 0; i < ALD; i++) {
            const int ch = tid + i * THREADS;
            const int row = ch >> 3, kc = (ch & 7) * 4;
            cp16(sb + row * PITCH + kc * 4,
                 A + (size_t)(mBase + row) * KDIM + k0 + kc);
        }
#pragma unroll
        for (int i = 0; i < BLD; i++) {
            const int ch = tid + i * THREADS;
            const int row = ch >> 3, kc = (ch & 7) * 4;
            const size_t g = (size_t)(nBase + row) * KDIM + k0 + kc;
            const uint32_t sa = sb + A_BYTES + row * PITCH + kc * 4;
            cp16(sa, Bt0 + g);
            if constexpr (DUAL) cp16(sa + B_BYTES, Bt1 + g);
        }
    };

    float acc0[2][NT][4];
    float acc1[2][DUAL ? NT : 1][4];
#pragma unroll
    for (int mt = 0; mt < 2; mt++)
#pragma unroll
        for (int nt = 0; nt < NT; nt++)
#pragma unroll
            for (int i = 0; i < 4; i++) {
                acc0[mt][nt][i] = 0.0f;
                if constexpr (DUAL) acc1[mt][nt][i] = 0.0f;
            }

    load_stage(0, 0);
    asm volatile("cp.async.commit_group;");
    load_stage(1, BK);
    asm volatile("cp.async.commit_group;");

    int cmp_st = 0, ld_st = 2;
#pragma unroll 1
    for (int kt = 0; kt < KT; kt++) {
        asm volatile("cp.async.wait_group 1;");
        __syncthreads();

        if (kt + 2 < KT) load_stage(ld_st, (kt + 2) * BK);
        asm volatile("cp.async.commit_group;");

        const uint32_t sb = sBase + cmp_st * STAGE;
#pragma unroll
        for (int kk = 0; kk < 4; kk++) {
            uint32_t a[2][4];
            ldsm4(a[0], sb + aOff + kk * 32);
            ldsm4(a[1], sb + aOff + 16 * PITCH + kk * 32);

            uint32_t b[NT / 2][4];
#pragma unroll
            for (int np = 0; np < NT / 2; np++)
                ldsm4(b[np], sb + bOff + np * 16 * PITCH + kk * 32);
#pragma unroll
            for (int mt = 0; mt < 2; mt++)
#pragma unroll
                for (int nt = 0; nt < NT; nt++)
                    mma_tf32(acc0[mt][nt], a[mt],
                             b[nt >> 1][(nt & 1) * 2], b[nt >> 1][(nt & 1) * 2 + 1]);

            if constexpr (DUAL) {
#pragma unroll
                for (int np = 0; np < NT / 2; np++)
                    ldsm4(b[np], sb + bOff + B_BYTES + np * 16 * PITCH + kk * 32);
#pragma unroll
                for (int mt = 0; mt < 2; mt++)
#pragma unroll
                    for (int nt = 0; nt < NT; nt++)
                        mma_tf32(acc1[mt][nt], a[mt],
                                 b[nt >> 1][(nt & 1) * 2], b[nt >> 1][(nt & 1) * 2 + 1]);
            }
        }
        cmp_st = (cmp_st == NSTAGE - 1) ? 0 : cmp_st + 1;
        ld_st  = (ld_st  == NSTAGE - 1) ? 0 : ld_st  + 1;
    }

    // epilogue: c0,c1 at (row g, cols 2t,2t+1); c2,c3 at row g+8
    const int r0b = mBase + wm * 32 + (lane >> 2);
    const int cb  = nBase + wn * WN + (lane & 3) * 2;
#pragma unroll
    for (int mt = 0; mt < 2; mt++) {
#pragma unroll
        for (int nt = 0; nt < NT; nt++) {
            const int c  = cb + nt * 8;
            const int r0 = r0b + mt * 16;
            const int r1 = r0 + 8;
            if constexpr (DUAL) {
                const float bq0 = bias0[c], bq1 = bias0[c + 1];
                const float bv0 = bias1[c], bv1 = bias1[c + 1];
                const float g00 = rna_tf32((acc1[mt][nt][0] + bv0) * sigmf(acc0[mt][nt][0] + bq0));
                const float g01 = rna_tf32((acc1[mt][nt][1] + bv1) * sigmf(acc0[mt][nt][1] + bq1));
                const float g10 = rna_tf32((acc1[mt][nt][2] + bv0) * sigmf(acc0[mt][nt][2] + bq0));
                const float g11 = rna_tf32((acc1[mt][nt][3] + bv1) * sigmf(acc0[mt][nt][3] + bq1));
                *reinterpret_cast<float2*>(C + (size_t)r0 * NDIM + c) = make_float2(g00, g01);
                *reinterpret_cast<float2*>(C + (size_t)r1 * NDIM + c) = make_float2(g10, g11);
            } else {
                const float b0v = bias0[c], b1v = bias0[c + 1];
                *reinterpret_cast<float2*>(C + (size_t)r0 * NDIM + c) =
                    make_float2(acc0[mt][nt][0] + b0v, acc0[mt][nt][1] + b1v);
                *reinterpret_cast<float2*>(C + (size_t)r1 * NDIM + c) =
                    make_float2(acc0[mt][nt][2] + b0v, acc0[mt][nt][3] + b1v);
            }
        }
    }
}

// ---------------------------------------------------------------------------
// launch
// ---------------------------------------------------------------------------
extern "C" void kernel_launch(void* const* d_in, const int* in_sizes, int n_in,
                              void* d_out, int out_size) {
    (void)in_sizes; (void)n_in; (void)out_size;
    const float* emb = (const float*)d_in[0];
    const float* Wq  = (const float*)d_in[1];
    const float* bq  = (const float*)d_in[2];
    // d_in[3]=Wk, d_in[4]=bk, d_in[7]=w: algebraically dead (num/den cancels to v)
    const float* Wv  = (const float*)d_in[5];
    const float* bv  = (const float*)d_in[6];
    const float* Wo  = (const float*)d_in[8];
    const float* bo  = (const float*)d_in[9];
    float* out = (float*)d_out;

    float *embr, *wqt, *wvt, *wot, *mid;
    cudaGetSymbolAddress((void**)&embr, g_emb_r);
    cudaGetSymbolAddress((void**)&wqt,  g_wq_t);
    cudaGetSymbolAddress((void**)&wvt,  g_wv_t);
    cudaGetSymbolAddress((void**)&wot,  g_wo_t);
    cudaGetSymbolAddress((void**)&mid,  g_mid);

    constexpr int SMEM = 3 * (128 * 144 + 2 * 64 * 144);  // 110592 (same for both variants)
    cudaFuncSetAttribute(gemm_tf32<true, 64>,   cudaFuncAttributeMaxDynamicSharedMemorySize, SMEM);
    cudaFuncSetAttribute(gemm_tf32<false, 128>, cudaFuncAttributeMaxDynamicSharedMemorySize, SMEM);

    // prepass: rna-round emb; rna-round + transpose the 3 live weight matrices
    const int n4 = M_TOT * KDIM / 4;
    round4_kernel<<<n4 / 256, 256>>>((const float4*)emb, (float4*)embr, n4);
    dim3 tb(32, 8), tg(32, 32);
    transpose_round_kernel<<<tg, tb>>>(Wq, wqt);
    transpose_round_kernel<<<tg, tb>>>(Wv, wvt);
    transpose_round_kernel<<<tg, tb>>>(Wo, wot);

    // g = rna( sigmoid(emb@Wq + bq) * (emb@Wv + bv) )
    dim3 g1(NDIM / 64, M_TOT / 128);   // (16, 64)
    gemm_tf32<true, 64><<<g1, 256, SMEM>>>(embr, wqt, wvt, bq, bv, mid);

    // out = g @ Wo + bo
    dim3 g2(NDIM / 128, M_TOT / 128);  // (8, 64)
    gemm_tf32<false, 128><<<g2, 256, SMEM>>>(mid, wot, nullptr, bo, nullptr, out);
}

// round 11
// speedup vs baseline: 1.7857x; 1.7857x over previous
#include <cuda_runtime.h>
#include <cuda_fp16.h>
#include <cstdint>
#include <cstddef>

// Problem constants: B=64, S=128, D_MODEL=1024, D_INNER=1024
#define M_TOT 8192
#define KDIM  1024
#define NDIM  1024

// Scratch (allowed: __device__ globals)
__device__ __align__(16) __half g_emb_h[(size_t)M_TOT * KDIM]; // fp16 embeddings
__device__ __align__(16) __half g_wq_t[(size_t)KDIM * NDIM];   // Wq^T fp16 [N][K]
__device__ __align__(16) __half g_wv_t[(size_t)KDIM * NDIM];   // Wv^T fp16
__device__ __align__(16) __half g_wo_t[(size_t)KDIM * NDIM];   // Wo^T fp16
__device__ __align__(16) __half g_mid[(size_t)M_TOT * NDIM];   // g = fp16(sigmoid(q)*v)

// ---------------------------------------------------------------------------
// helpers
// ---------------------------------------------------------------------------
__device__ __forceinline__ uint32_t h2u(__half2 h) {
    return *reinterpret_cast<uint32_t*>(&h);
}

__device__ __forceinline__ void cp16(uint32_t saddr, const void* gptr) {
    asm volatile("cp.async.cg.shared.global [%0], [%1], 16;" :: "r"(saddr), "l"(gptr));
}

__device__ __forceinline__ void ldsm4(uint32_t r[4], uint32_t saddr) {
    asm volatile("ldmatrix.sync.aligned.m8n8.x4.shared.b16 {%0,%1,%2,%3}, [%4];"
                 : "=r"(r[0]), "=r"(r[1]), "=r"(r[2]), "=r"(r[3]) : "r"(saddr));
}

// fp16 mma, fp32 accumulate: C(16x8) += A(16x16) @ B(16x8)
__device__ __forceinline__ void mma_f16(float c[4], const uint32_t a[4],
                                        uint32_t b0, uint32_t b1) {
    asm volatile(
        "mma.sync.aligned.m16n8k16.row.col.f32.f16.f16.f32 "
        "{%0,%1,%2,%3},{%4,%5,%6,%7},{%8,%9},{%0,%1,%2,%3};"
        : "+f"(c[0]), "+f"(c[1]), "+f"(c[2]), "+f"(c[3])
        : "r"(a[0]), "r"(a[1]), "r"(a[2]), "r"(a[3]), "r"(b0), "r"(b1));
}

__device__ __forceinline__ float sigmf(float x) {
    return 1.0f / (1.0f + __expf(-x));
}

// ---------------------------------------------------------------------------
// Prepass kernels: fp32 -> fp16 (RN), weights also transposed to [N][K]
// ---------------------------------------------------------------------------
__global__ void f2h_kernel(const float4* __restrict__ in, uint4* __restrict__ out, int n8) {
    int i = blockIdx.x * blockDim.x + threadIdx.x;
    if (i < n8) {
        float4 a = in[2 * i], b = in[2 * i + 1];
        uint4 o;
        o.x = h2u(__float22half2_rn(make_float2(a.x, a.y)));
        o.y = h2u(__float22half2_rn(make_float2(a.z, a.w)));
        o.z = h2u(__float22half2_rn(make_float2(b.x, b.y)));
        o.w = h2u(__float22half2_rn(make_float2(b.z, b.w)));
        out[i] = o;
    }
}

// out[n][k] = fp16(in[k][n]) for a 1024x1024 matrix
__global__ void transpose_h_kernel(const float* __restrict__ in, __half* __restrict__ out) {
    __shared__ float tile[32][33];
    const int bx = blockIdx.x * 32;  // n-block
    const int by = blockIdx.y * 32;  // k-block
    const int tx = threadIdx.x, ty = threadIdx.y;
#pragma unroll
    for (int j = 0; j < 4; j++)
        tile[ty + j * 8][tx] = in[(size_t)(by + ty + j * 8) * NDIM + bx + tx];
    __syncthreads();
#pragma unroll
    for (int j = 0; j < 4; j++)
        out[(size_t)(bx + ty + j * 8) * KDIM + by + tx] = __float2half_rn(tile[tx][ty + j * 8]);
}

// ---------------------------------------------------------------------------
// FP16 tensor-core GEMM (fp32 accum).
//   DUAL=true : Ch = fp16( sigmoid(A@B0^T + bias0) * (A@B1^T + bias1) )
//   DUAL=false: Cf = A@B0^T + bias0
// A: [M][K] fp16 row-major.  Bt*: [N][K] fp16 row-major (pre-transposed).
// BM=128, BK=64, 256 threads, warp grid 4(m) x 2(n), warp tile 32 x (BN/2).
// Byte-geometry of smem/ldmatrix identical to the proven TF32 R8 kernel.
// ---------------------------------------------------------------------------
template <bool DUAL, int BN>
__global__ __launch_bounds__(256, 1)
void gemm_f16(const __half* __restrict__ A, const __half* __restrict__ Bt0,
              const __half* __restrict__ Bt1, const float* __restrict__ bias0,
              const float* __restrict__ bias1, void* __restrict__ Cv) {
    constexpr int BM = 128, BK = 64, THREADS = 256, NSTAGE = 3;
    constexpr int WN = BN / 2;
    constexpr int NT = WN / 8;                 // n8-tiles per warp (4 or 8)
    constexpr int PITCH = 144;                 // bytes per smem row (BK*2=128 + 16 pad)
    constexpr int A_BYTES = BM * PITCH;        // 18432
    constexpr int B_BYTES = BN * PITCH;
    constexpr int NB = DUAL ? 2 : 1;
    constexpr int STAGE = A_BYTES + B_BYTES * NB;
    constexpr int KT = KDIM / BK;              // 16
    constexpr int ALD = BM * 8 / THREADS;      // 4
    constexpr int BLD = BN * 8 / THREADS;      // 2 (BN=64) or 4 (BN=128)
    constexpr int OFF_BIAS = NSTAGE * STAGE;

    extern __shared__ char smem[];
    const int tid  = threadIdx.x;
    const int lane = tid & 31, warp = tid >> 5;
    const int wm = warp >> 1, wn = warp & 1;
    const int mBase = blockIdx.y * BM, nBase = blockIdx.x * BN;

    const uint32_t sBase = (uint32_t)__cvta_generic_to_shared(smem);

    {   // stage biases into smem for the epilogue
        float* bsw = reinterpret_cast<float*>(smem + OFF_BIAS);
        for (int i = tid; i < BN; i += THREADS) {
            bsw[i] = bias0[nBase + i];
            if constexpr (DUAL) bsw[BN + i] = bias1[nBase + i];
        }
    }

    // lane-dependent ldmatrix source offsets (bytes within a stage).
    // A atom: 16 rows x 32B (k0-15);  B atom: 8 n-rows x 32B (k0-15), x2 n-tiles.
    const int lt = lane >> 3, lr = lane & 7;
    const uint32_t aOff = (uint32_t)((wm * 32 + (lt & 1) * 8 + lr) * PITCH + (lt >> 1) * 16);
    const uint32_t bOff = (uint32_t)(A_BYTES + (wn * WN + (lt >> 1) * 8 + lr) * PITCH + (lt & 1) * 16);

    auto load_stage = [&](int st, int k0) {   // k0 in halfs
        const uint32_t sb = sBase + st * STAGE;
#pragma unroll
        for (int i = 0; i < ALD; i++) {
            const int ch = tid + i * THREADS;
            const int row = ch >> 3, kc = ch & 7;           // 8 x 16B chunks per row
            cp16(sb + row * PITCH + kc * 16,
                 A + (size_t)(mBase + row) * KDIM + k0 + kc * 8);
        }
#pragma unroll
        for (int i = 0; i < BLD; i++) {
            const int ch = tid + i * THREADS;
            const int row = ch >> 3, kc = ch & 7;
            const size_t g = (size_t)(nBase + row) * KDIM + k0 + kc * 8;
            const uint32_t sa = sb + A_BYTES + row * PITCH + kc * 16;
            cp16(sa, Bt0 + g);
            if constexpr (DUAL) cp16(sa + B_BYTES, Bt1 + g);
        }
    };

    float acc0[2][NT][4];
    float acc1[2][DUAL ? NT : 1][4];
#pragma unroll
    for (int mt = 0; mt < 2; mt++)
#pragma unroll
        for (int nt = 0; nt < NT; nt++)
#pragma unroll
            for (int i = 0; i < 4; i++) {
                acc0[mt][nt][i] = 0.0f;
                if constexpr (DUAL) acc1[mt][nt][i] = 0.0f;
            }

    load_stage(0, 0);
    asm volatile("cp.async.commit_group;");
    load_stage(1, BK);
    asm volatile("cp.async.commit_group;");

    int cmp_st = 0, ld_st = 2;
#pragma unroll 1
    for (int kt = 0; kt < KT; kt++) {
        asm volatile("cp.async.wait_group 1;");
        __syncthreads();

        if (kt + 2 < KT) load_stage(ld_st, (kt + 2) * BK);
        asm volatile("cp.async.commit_group;");

        const uint32_t sb = sBase + cmp_st * STAGE;
#pragma unroll
        for (int kk = 0; kk < 4; kk++) {               // 4 x k16 per BK=64 stage
            uint32_t a[2][4];
            ldsm4(a[0], sb + aOff + kk * 32);
            ldsm4(a[1], sb + aOff + 16 * PITCH + kk * 32);

            uint32_t b[NT / 2][4];
#pragma unroll
            for (int np = 0; np < NT / 2; np++)
                ldsm4(b[np], sb + bOff + np * 16 * PITCH + kk * 32);
#pragma unroll
            for (int mt = 0; mt < 2; mt++)
#pragma unroll
                for (int nt = 0; nt < NT; nt++)
                    mma_f16(acc0[mt][nt], a[mt],
                            b[nt >> 1][(nt & 1) * 2], b[nt >> 1][(nt & 1) * 2 + 1]);

            if constexpr (DUAL) {
#pragma unroll
                for (int np = 0; np < NT / 2; np++)
                    ldsm4(b[np], sb + bOff + B_BYTES + np * 16 * PITCH + kk * 32);
#pragma unroll
                for (int mt = 0; mt < 2; mt++)
#pragma unroll
                    for (int nt = 0; nt < NT; nt++)
                        mma_f16(acc1[mt][nt], a[mt],
                                b[nt >> 1][(nt & 1) * 2], b[nt >> 1][(nt & 1) * 2 + 1]);
            }
        }
        cmp_st = (cmp_st == NSTAGE - 1) ? 0 : cmp_st + 1;
        ld_st  = (ld_st  == NSTAGE - 1) ? 0 : ld_st  + 1;
    }

    // epilogue: c0,c1 at (row g, cols 2t,2t+1); c2,c3 at row g+8
    const float* bsr = reinterpret_cast<const float*>(smem + OFF_BIAS);
    const int r0b = mBase + wm * 32 + (lane >> 2);
    const int cbl = wn * WN + (lane & 3) * 2;   // column within block tile
#pragma unroll
    for (int mt = 0; mt < 2; mt++) {
#pragma unroll
        for (int nt = 0; nt < NT; nt++) {
            const int cl = cbl + nt * 8;        // local col
            const int c  = nBase + cl;          // global col
            const int r0 = r0b + mt * 16;
            const int r1 = r0 + 8;
            if constexpr (DUAL) {
                __half* C = reinterpret_cast<__half*>(Cv);
                const float bq0 = bsr[cl], bq1 = bsr[cl + 1];
                const float bv0 = bsr[BN + cl], bv1 = bsr[BN + cl + 1];
                const float g00 = (acc1[mt][nt][0] + bv0) * sigmf(acc0[mt][nt][0] + bq0);
                const float g01 = (acc1[mt][nt][1] + bv1) * sigmf(acc0[mt][nt][1] + bq1);
                const float g10 = (acc1[mt][nt][2] + bv0) * sigmf(acc0[mt][nt][2] + bq0);
                const float g11 = (acc1[mt][nt][3] + bv1) * sigmf(acc0[mt][nt][3] + bq1);
                *reinterpret_cast<__half2*>(C + (size_t)r0 * NDIM + c) =
                    __float22half2_rn(make_float2(g00, g01));
                *reinterpret_cast<__half2*>(C + (size_t)r1 * NDIM + c) =
                    __float22half2_rn(make_float2(g10, g11));
            } else {
                float* C = reinterpret_cast<float*>(Cv);
                const float b0v = bsr[cl], b1v = bsr[cl + 1];
                *reinterpret_cast<float2*>(C + (size_t)r0 * NDIM + c) =
                    make_float2(acc0[mt][nt][0] + b0v, acc0[mt][nt][1] + b1v);
                *reinterpret_cast<float2*>(C + (size_t)r1 * NDIM + c) =
                    make_float2(acc0[mt][nt][2] + b0v, acc0[mt][nt][3] + b1v);
            }
        }
    }
}

// ---------------------------------------------------------------------------
// launch
// ---------------------------------------------------------------------------
extern "C" void kernel_launch(void* const* d_in, const int* in_sizes, int n_in,
                              void* d_out, int out_size) {
    (void)in_sizes; (void)n_in; (void)out_size;
    const float* emb = (const float*)d_in[0];
    const float* Wq  = (const float*)d_in[1];
    const float* bq  = (const float*)d_in[2];
    // d_in[3]=Wk, d_in[4]=bk, d_in[7]=w: algebraically dead (num/den cancels to v)
    const float* Wv  = (const float*)d_in[5];
    const float* bv  = (const float*)d_in[6];
    const float* Wo  = (const float*)d_in[8];
    const float* bo  = (const float*)d_in[9];
    float* out = (float*)d_out;

    __half *embh, *wqt, *wvt, *wot, *mid;
    cudaGetSymbolAddress((void**)&embh, g_emb_h);
    cudaGetSymbolAddress((void**)&wqt,  g_wq_t);
    cudaGetSymbolAddress((void**)&wvt,  g_wv_t);
    cudaGetSymbolAddress((void**)&wot,  g_wo_t);
    cudaGetSymbolAddress((void**)&mid,  g_mid);

    // smem: 3 stages + bias block. Dual(BN=64) and single(BN=128) are equal.
    constexpr int SMEM1 = 3 * (128 * 144 + 2 * 64 * 144) + 1024;   // 111616
    constexpr int SMEM2 = 3 * (128 * 144 + 128 * 144) + 1024;      // 111616
    cudaFuncSetAttribute(gemm_f16<true, 64>,
                         cudaFuncAttributeMaxDynamicSharedMemorySize, SMEM1);
    cudaFuncSetAttribute(gemm_f16<false, 128>,
                         cudaFuncAttributeMaxDynamicSharedMemorySize, SMEM2);

    // prepass: fp32 -> fp16 for emb; transpose+convert the 3 live weights
    const int n8 = M_TOT * KDIM / 8;
    f2h_kernel<<<n8 / 256, 256>>>((const float4*)emb, (uint4*)embh, n8);
    dim3 tb(32, 8), tg(32, 32);
    transpose_h_kernel<<<tg, tb>>>(Wq, wqt);
    transpose_h_kernel<<<tg, tb>>>(Wv, wvt);
    transpose_h_kernel<<<tg, tb>>>(Wo, wot);

    // g = fp16( sigmoid(emb@Wq + bq) * (emb@Wv + bv) )
    dim3 g1(NDIM / 64, M_TOT / 128);   // (16, 64)
    gemm_f16<true, 64><<<g1, 256, SMEM1>>>(embh, wqt, wvt, bq, bv, (void*)mid);

    // out = g @ Wo + bo
    dim3 g2(NDIM / 128, M_TOT / 128);  // (8, 64)
    gemm_f16<false, 128><<<g2, 256, SMEM2>>>(mid, wot, nullptr, bo, nullptr, (void*)out);
}

// round 12
// speedup vs baseline: 1.9768x; 1.1070x over previous
#include <cuda_runtime.h>
#include <cuda_fp16.h>
#include <cstdint>
#include <cstddef>

// Problem constants: B=64, S=128, D_MODEL=1024, D_INNER=1024
#define M_TOT 8192
#define KDIM  1024
#define NDIM  1024

// Scratch (allowed: __device__ globals)
__device__ __align__(16) __half g_emb_h[(size_t)M_TOT * KDIM]; // fp16 embeddings
__device__ __align__(16) __half g_wq_t[(size_t)KDIM * NDIM];   // Wq^T fp16 [N][K]
__device__ __align__(16) __half g_wv_t[(size_t)KDIM * NDIM];   // Wv^T fp16
__device__ __align__(16) __half g_wo_t[(size_t)KDIM * NDIM];   // Wo^T fp16
__device__ __align__(16) __half g_mid[(size_t)M_TOT * NDIM];   // g = fp16(sigmoid(q)*v)

// ---------------------------------------------------------------------------
// helpers
// ---------------------------------------------------------------------------
__device__ __forceinline__ uint32_t h2u(__half2 h) {
    return *reinterpret_cast<uint32_t*>(&h);
}

__device__ __forceinline__ void cp16(uint32_t saddr, const void* gptr) {
    asm volatile("cp.async.cg.shared.global [%0], [%1], 16;" :: "r"(saddr), "l"(gptr));
}

__device__ __forceinline__ void ldsm4(uint32_t r[4], uint32_t saddr) {
    asm volatile("ldmatrix.sync.aligned.m8n8.x4.shared.b16 {%0,%1,%2,%3}, [%4];"
                 : "=r"(r[0]), "=r"(r[1]), "=r"(r[2]), "=r"(r[3]) : "r"(saddr));
}

// fp16 mma, fp32 accumulate: C(16x8) += A(16x16) @ B(16x8)
__device__ __forceinline__ void mma_f16(float c[4], const uint32_t a[4],
                                        uint32_t b0, uint32_t b1) {
    asm volatile(
        "mma.sync.aligned.m16n8k16.row.col.f32.f16.f16.f32 "
        "{%0,%1,%2,%3},{%4,%5,%6,%7},{%8,%9},{%0,%1,%2,%3};"
        : "+f"(c[0]), "+f"(c[1]), "+f"(c[2]), "+f"(c[3])
        : "r"(a[0]), "r"(a[1]), "r"(a[2]), "r"(a[3]), "r"(b0), "r"(b1));
}

__device__ __forceinline__ float sigmf(float x) {
    return 1.0f / (1.0f + __expf(-x));
}

// ---------------------------------------------------------------------------
// Prepass kernels: fp32 -> fp16 (RN), weights also transposed to [N][K]
// ---------------------------------------------------------------------------
__global__ void f2h_kernel(const float4* __restrict__ in, uint4* __restrict__ out, int n8) {
    int i = blockIdx.x * blockDim.x + threadIdx.x;
    if (i < n8) {
        float4 a = in[2 * i], b = in[2 * i + 1];
        uint4 o;
        o.x = h2u(__float22half2_rn(make_float2(a.x, a.y)));
        o.y = h2u(__float22half2_rn(make_float2(a.z, a.w)));
        o.z = h2u(__float22half2_rn(make_float2(b.x, b.y)));
        o.w = h2u(__float22half2_rn(make_float2(b.z, b.w)));
        out[i] = o;
    }
}

// out[n][k] = fp16(in[k][n]) for a 1024x1024 matrix
__global__ void transpose_h_kernel(const float* __restrict__ in, __half* __restrict__ out) {
    __shared__ float tile[32][33];
    const int bx = blockIdx.x * 32;  // n-block
    const int by = blockIdx.y * 32;  // k-block
    const int tx = threadIdx.x, ty = threadIdx.y;
#pragma unroll
    for (int j = 0; j < 4; j++)
        tile[ty + j * 8][tx] = in[(size_t)(by + ty + j * 8) * NDIM + bx + tx];
    __syncthreads();
#pragma unroll
    for (int j = 0; j < 4; j++)
        out[(size_t)(bx + ty + j * 8) * KDIM + by + tx] = __float2half_rn(tile[tx][ty + j * 8]);
}

// ---------------------------------------------------------------------------
// FP16 tensor-core GEMM (fp32 accum), 2 CTAs/SM.
//   DUAL=true : BN=64,  warp grid 2m x 4n (warp tile 64x16 per operand)
//               Ch = fp16( sigmoid(A@B0^T + bias0) * (A@B1^T + bias1) )
//   DUAL=false: BN=128, warp grid 4m x 2n (warp tile 32x64)
//               Cf = A@B0^T + bias0
// A: [M][K] fp16 row-major.  Bt*: [N][K] fp16 row-major (pre-transposed).
// BM=128, BK=32 (PITCH=80B: conflict-free STS and LDSM), 4-stage ring.
// ---------------------------------------------------------------------------
template <bool DUAL, int BN>
__global__ __launch_bounds__(256, 2)
void gemm_f16(const __half* __restrict__ A, const __half* __restrict__ Bt0,
              const __half* __restrict__ Bt1, const float* __restrict__ bias0,
              const float* __restrict__ bias1, void* __restrict__ Cv) {
    constexpr int BM = 128, BK = 32, THREADS = 256, NSTAGE = 4;
    constexpr int WMW = DUAL ? 2 : 4;          // warps along m
    constexpr int WNW = 8 / WMW;               // warps along n
    constexpr int WM = BM / WMW;               // 64 / 32
    constexpr int WN = BN / WNW;               // 16 / 64
    constexpr int MT = WM / 16;                // 4 / 2   (m16 tiles per warp)
    constexpr int NT = WN / 8;                 // 2 / 8   (n8 tiles per warp)
    constexpr int PITCH = 80;                  // BK*2=64B + 16B pad (bank-disjoint)
    constexpr int A_BYTES = BM * PITCH;        // 10240
    constexpr int B_BYTES = BN * PITCH;        // 5120 (dual) / 10240 (single)
    constexpr int NB = DUAL ? 2 : 1;
    constexpr int STAGE = A_BYTES + B_BYTES * NB;   // 20480 both variants
    constexpr int KT = KDIM / BK;              // 32
    constexpr int ALD = BM * 4 / THREADS;      // 2 (16B chunks per thread, A)
    constexpr int BLD = BN * 4 / THREADS;      // 1 (dual) / 2 (single)
    constexpr int OFF_BIAS = NSTAGE * STAGE;

    extern __shared__ char smem[];
    const int tid  = threadIdx.x;
    const int lane = tid & 31, warp = tid >> 5;
    const int wm = warp / WNW, wn = warp % WNW;
    const int mBase = blockIdx.y * BM, nBase = blockIdx.x * BN;

    const uint32_t sBase = (uint32_t)__cvta_generic_to_shared(smem);

    {   // stage biases into smem for the epilogue
        float* bsw = reinterpret_cast<float*>(smem + OFF_BIAS);
        for (int i = tid; i < BN; i += THREADS) {
            bsw[i] = bias0[nBase + i];
            if constexpr (DUAL) bsw[BN + i] = bias1[nBase + i];
        }
    }

    // lane-dependent ldmatrix source offsets (bytes within a stage).
    // A atom: 16 rows x 32B;  B atom: 16 n-rows x 32B (2 n8-tiles x 2 k-halves).
    const int lt = lane >> 3, lr = lane & 7;
    const uint32_t aOff = (uint32_t)((wm * WM + (lt & 1) * 8 + lr) * PITCH + (lt >> 1) * 16);
    const uint32_t bOff = (uint32_t)(A_BYTES + (wn * WN + (lt >> 1) * 8 + lr) * PITCH + (lt & 1) * 16);

    auto load_stage = [&](int st, int k0) {   // k0 in halfs
        const uint32_t sb = sBase + st * STAGE;
#pragma unroll
        for (int i = 0; i < ALD; i++) {
            const int ch = tid + i * THREADS;
            const int row = ch >> 2, kc = ch & 3;           // 4 x 16B chunks per row
            cp16(sb + row * PITCH + kc * 16,
                 A + (size_t)(mBase + row) * KDIM + k0 + kc * 8);
        }
#pragma unroll
        for (int i = 0; i < BLD; i++) {
            const int ch = tid + i * THREADS;
            const int row = ch >> 2, kc = ch & 3;
            const size_t g = (size_t)(nBase + row) * KDIM + k0 + kc * 8;
            const uint32_t sa = sb + A_BYTES + row * PITCH + kc * 16;
            cp16(sa, Bt0 + g);
            if constexpr (DUAL) cp16(sa + B_BYTES, Bt1 + g);
        }
    };

    float acc0[MT][NT][4];
    float acc1[DUAL ? MT : 1][DUAL ? NT : 1][4];
#pragma unroll
    for (int mt = 0; mt < MT; mt++)
#pragma unroll
        for (int nt = 0; nt < NT; nt++)
#pragma unroll
            for (int i = 0; i < 4; i++) {
                acc0[mt][nt][i] = 0.0f;
                if constexpr (DUAL) acc1[mt][nt][i] = 0.0f;
            }

#pragma unroll
    for (int st = 0; st < NSTAGE - 1; st++) {
        load_stage(st, st * BK);
        asm volatile("cp.async.commit_group;");
    }

#pragma unroll 1
    for (int kt = 0; kt < KT; kt++) {
        const int cmp_st = kt & (NSTAGE - 1);
        asm volatile("cp.async.wait_group 2;");
        __syncthreads();

        if (kt + NSTAGE - 1 < KT)
            load_stage((kt + NSTAGE - 1) & (NSTAGE - 1), (kt + NSTAGE - 1) * BK);
        asm volatile("cp.async.commit_group;");

        const uint32_t sb = sBase + cmp_st * STAGE;
#pragma unroll
        for (int kk = 0; kk < 2; kk++) {               // 2 x k16 per BK=32 stage
            uint32_t a[MT][4];
#pragma unroll
            for (int mt = 0; mt < MT; mt++)
                ldsm4(a[mt], sb + aOff + mt * 16 * PITCH + kk * 32);

            uint32_t b[NT / 2][4];
#pragma unroll
            for (int np = 0; np < NT / 2; np++)
                ldsm4(b[np], sb + bOff + np * 16 * PITCH + kk * 32);
#pragma unroll
            for (int mt = 0; mt < MT; mt++)
#pragma unroll
                for (int nt = 0; nt < NT; nt++)
                    mma_f16(acc0[mt][nt], a[mt],
                            b[nt >> 1][(nt & 1) * 2], b[nt >> 1][(nt & 1) * 2 + 1]);

            if constexpr (DUAL) {
#pragma unroll
                for (int np = 0; np < NT / 2; np++)
                    ldsm4(b[np], sb + bOff + B_BYTES + np * 16 * PITCH + kk * 32);
#pragma unroll
                for (int mt = 0; mt < MT; mt++)
#pragma unroll
                    for (int nt = 0; nt < NT; nt++)
                        mma_f16(acc1[mt][nt], a[mt],
                                b[nt >> 1][(nt & 1) * 2], b[nt >> 1][(nt & 1) * 2 + 1]);
            }
        }
    }

    // epilogue: c0,c1 at (row g, cols 2t,2t+1); c2,c3 at row g+8
    const float* bsr = reinterpret_cast<const float*>(smem + OFF_BIAS);
    const int r0b = mBase + wm * WM + (lane >> 2);
    const int cbl = wn * WN + (lane & 3) * 2;   // column within block tile
#pragma unroll
    for (int mt = 0; mt < MT; mt++) {
#pragma unroll
        for (int nt = 0; nt < NT; nt++) {
            const int cl = cbl + nt * 8;        // local col
            const int c  = nBase + cl;          // global col
            const int r0 = r0b + mt * 16;
            const int r1 = r0 + 8;
            if constexpr (DUAL) {
                __half* C = reinterpret_cast<__half*>(Cv);
                const float bq0 = bsr[cl], bq1 = bsr[cl + 1];
                const float bv0 = bsr[BN + cl], bv1 = bsr[BN + cl + 1];
                const float g00 = (acc1[mt][nt][0] + bv0) * sigmf(acc0[mt][nt][0] + bq0);
                const float g01 = (acc1[mt][nt][1] + bv1) * sigmf(acc0[mt][nt][1] + bq1);
                const float g10 = (acc1[mt][nt][2] + bv0) * sigmf(acc0[mt][nt][2] + bq0);
                const float g11 = (acc1[mt][nt][3] + bv1) * sigmf(acc0[mt][nt][3] + bq1);
                *reinterpret_cast<__half2*>(C + (size_t)r0 * NDIM + c) =
                    __float22half2_rn(make_float2(g00, g01));
                *reinterpret_cast<__half2*>(C + (size_t)r1 * NDIM + c) =
                    __float22half2_rn(make_float2(g10, g11));
            } else {
                float* C = reinterpret_cast<float*>(Cv);
                const float b0v = bsr[cl], b1v = bsr[cl + 1];
                *reinterpret_cast<float2*>(C + (size_t)r0 * NDIM + c) =
                    make_float2(acc0[mt][nt][0] + b0v, acc0[mt][nt][1] + b1v);
                *reinterpret_cast<float2*>(C + (size_t)r1 * NDIM + c) =
                    make_float2(acc0[mt][nt][2] + b0v, acc0[mt][nt][3] + b1v);
            }
        }
    }
}

// ---------------------------------------------------------------------------
// launch
// ---------------------------------------------------------------------------
extern "C" void kernel_launch(void* const* d_in, const int* in_sizes, int n_in,
                              void* d_out, int out_size) {
    (void)in_sizes; (void)n_in; (void)out_size;
    const float* emb = (const float*)d_in[0];
    const float* Wq  = (const float*)d_in[1];
    const float* bq  = (const float*)d_in[2];
    // d_in[3]=Wk, d_in[4]=bk, d_in[7]=w: algebraically dead (num/den cancels to v)
    const float* Wv  = (const float*)d_in[5];
    const float* bv  = (const float*)d_in[6];
    const float* Wo  = (const float*)d_in[8];
    const float* bo  = (const float*)d_in[9];
    float* out = (float*)d_out;

    __half *embh, *wqt, *wvt, *wot, *mid;
    cudaGetSymbolAddress((void**)&embh, g_emb_h);
    cudaGetSymbolAddress((void**)&wqt,  g_wq_t);
    cudaGetSymbolAddress((void**)&wvt,  g_wv_t);
    cudaGetSymbolAddress((void**)&wot,  g_wo_t);
    cudaGetSymbolAddress((void**)&mid,  g_mid);

    // smem: 4 stages of 20480B + bias block -> 2 CTAs/SM
    constexpr int SMEM1 = 4 * 20480 + 1024;   // 82944 (dual)
    constexpr int SMEM2 = 4 * 20480 + 1024;   // 82944 (single)
    cudaFuncSetAttribute(gemm_f16<true, 64>,
                         cudaFuncAttributeMaxDynamicSharedMemorySize, SMEM1);
    cudaFuncSetAttribute(gemm_f16<false, 128>,
                         cudaFuncAttributeMaxDynamicSharedMemorySize, SMEM2);

    // prepass: fp32 -> fp16 for emb; transpose+convert the 3 live weights
    const int n8 = M_TOT * KDIM / 8;
    f2h_kernel<<<n8 / 256, 256>>>((const float4*)emb, (uint4*)embh, n8);
    dim3 tb(32, 8), tg(32, 32);
    transpose_h_kernel<<<tg, tb>>>(Wq, wqt);
    transpose_h_kernel<<<tg, tb>>>(Wv, wvt);
    transpose_h_kernel<<<tg, tb>>>(Wo, wot);

    // g = fp16( sigmoid(emb@Wq + bq) * (emb@Wv + bv) )
    dim3 g1(NDIM / 64, M_TOT / 128);   // (16, 64)
    gemm_f16<true, 64><<<g1, 256, SMEM1>>>(embh, wqt, wvt, bq, bv, (void*)mid);

    // out = g @ Wo + bo
    dim3 g2(NDIM / 128, M_TOT / 128);  // (8, 64)
    gemm_f16<false, 128><<<g2, 256, SMEM2>>>(mid, wot, nullptr, bo, nullptr, (void*)out);
}